// round 13
// baseline (speedup 1.0000x reference)
#include <cuda_runtime.h>
#include <cuda_bf16.h>
#include <math.h>
#include <stdint.h>

#define T_DIM 8192
#define D_DIM 128
#define BM 128
#define BN 64
#define NTH 256
#define NCTA 148
#define FT_TOTAL 8192            /* 64 rowblocks * 128 keytiles */
#define LOG2E 1.4426950408889634f

/* smem: THREE 32KB K buffers (KH 16K | KL 16K) + qbias triple buffer */
#define BUF_STRIDE 32768
#define OFF_KL_REL 16384
#define OFF_QB (3 * BUF_STRIDE)           /* 98304 */
#define SMEM_SZ (OFF_QB + 3 * 256 + 128)  /* 99200 */

__device__ float  g_qbias[T_DIM];
__device__ float  g_O[4 * T_DIM * D_DIM];     /* 4 slots; unwritten stay 0 */
__device__ float4 g_ml[4 * T_DIM];            /* (m_scale, p_max, l, 0)    */
__device__ float  g_b[T_DIM];
__device__ float  g_hpart[1024 * D_DIM];
__device__ float  g_h2[64 * D_DIM];
__device__ float  g_h[D_DIM];

__device__ __forceinline__ uint32_t smem_u32(const void* p) {
    uint32_t a;
    asm("{ .reg .u64 t; cvta.to.shared.u64 t, %1; cvt.u32.u64 %0, t; }" : "=r"(a) : "l"(p));
    return a;
}
__device__ __forceinline__ float ex2(float x) {
    float y;
    asm("ex2.approx.f32 %0, %1;" : "=f"(y) : "f"(x));
    return y;
}
__device__ __forceinline__ uint32_t pack_bf16x2(float lo, float hi) {
    uint32_t r;
    asm("cvt.rn.bf16x2.f32 %0, %1, %2;" : "=r"(r) : "f"(hi), "f"(lo));
    return r;
}
__device__ __forceinline__ void split2(float a, float b, uint32_t& hi, uint32_t& lo) {
    hi = pack_bf16x2(a, b);
    float fa = __uint_as_float(hi << 16);
    float fb = __uint_as_float(hi & 0xffff0000u);
    lo = pack_bf16x2(a - fa, b - fb);
}

#define LDSM4(r, addr) \
    asm volatile("ldmatrix.sync.aligned.m8n8.x4.shared.b16 {%0,%1,%2,%3}, [%4];" \
        : "=r"((r)[0]), "=r"((r)[1]), "=r"((r)[2]), "=r"((r)[3]) : "r"(addr))
#define LDSM4T(r, addr) \
    asm volatile("ldmatrix.sync.aligned.m8n8.x4.trans.shared.b16 {%0,%1,%2,%3}, [%4];" \
        : "=r"((r)[0]), "=r"((r)[1]), "=r"((r)[2]), "=r"((r)[3]) : "r"(addr))
#define MMA(c, a, b) \
    asm volatile("mma.sync.aligned.m16n8k16.row.col.f32.bf16.bf16.f32 " \
        "{%0,%1,%2,%3}, {%4,%5,%6,%7}, {%8,%9}, {%0,%1,%2,%3};" \
        : "+f"((c)[0]), "+f"((c)[1]), "+f"((c)[2]), "+f"((c)[3]) \
        : "r"((a)[0]), "r"((a)[1]), "r"((a)[2]), "r"((a)[3]), "r"((b)[0]), "r"((b)[1]))

/* ================= K0: qbias[j] = (question[j] . w_q) * log2(e) ================= */
__global__ void qbias_kernel(const float* __restrict__ x, const float* __restrict__ kern) {
    int j = blockIdx.x * 8 + (threadIdx.x >> 5);
    int lane = threadIdx.x & 31;
    const float* q  = x + (size_t)T_DIM * D_DIM + (size_t)j * D_DIM;
    const float* wq = kern + D_DIM;
    float s = q[lane] * wq[lane] + q[lane + 32] * wq[lane + 32]
            + q[lane + 64] * wq[lane + 64] + q[lane + 96] * wq[lane + 96];
    #pragma unroll
    for (int off = 16; off; off >>= 1) s += __shfl_xor_sync(0xffffffffu, s, off);
    if (lane == 0) g_qbias[j] = s * LOG2E;
}

/* ================= K1: HMMA flash, deferred-GEMM2 pipeline ================= */
__global__ void __launch_bounds__(NTH, 1)
flash_kernel(const float* __restrict__ x, const float* __restrict__ kern)
{
    extern __shared__ char smem[];
    const uint32_t sb = smem_u32(smem);

    const int tid  = threadIdx.x;
    const int lane = tid & 31;
    const int w    = tid >> 5;
    const int cta  = blockIdx.x;
    const int ft0  = (FT_TOTAL * cta) / NCTA;
    const int ft1  = (FT_TOTAL * (cta + 1)) / NCTA;
    const int slot = cta & 3;

    const float* ctx = x;
    const float* qst = x + (size_t)T_DIM * D_DIM;
    const float* wm  = kern + 2 * D_DIM;

    const int m0 = w * 16;
    const int a_row = m0 + (lane & 15);
    const int a_cs  = (lane >> 4);
    const int b1_key = ((lane >> 4) << 3) + (lane & 7);
    const int b1_cs  = ((lane >> 3) & 1);
    const int b2_key = ((lane >> 3) & 1) * 8 + (lane & 7);
    const int b2_cs  = (lane >> 4);
    const int srow = tid >> 4, sch = tid & 15;

    int ft = ft0;
    while (ft < ft1) {
        const int ra   = ft >> 7;
        const int tend = min(ft1, (ra + 1) << 7);
        const int kt0  = ft & 127;
        const int ntl  = tend - ft;
        const int row0 = ra * BM;

        __syncthreads();   /* prior segment fully done with smem */

        /* ---- prologue A: Q' = ctx*w_m*log2e → bf16 hi/lo staged in bufs 0/1 ---- */
        #pragma unroll
        for (int i = 0; i < 8; ++i) {
            int idx = tid + i * NTH;
            int row = idx >> 4, ch = idx & 15;
            const float* src = ctx + (size_t)(row0 + row) * D_DIM + ch * 8;
            float4 v0 = *(const float4*)src, v1 = *(const float4*)(src + 4);
            float4 w0 = *(const float4*)&wm[ch * 8], w1 = *(const float4*)&wm[ch * 8 + 4];
            w0.x *= LOG2E; w0.y *= LOG2E; w0.z *= LOG2E; w0.w *= LOG2E;
            w1.x *= LOG2E; w1.y *= LOG2E; w1.z *= LOG2E; w1.w *= LOG2E;
            v0.x *= w0.x; v0.y *= w0.y; v0.z *= w0.z; v0.w *= w0.w;
            v1.x *= w1.x; v1.y *= w1.y; v1.z *= w1.z; v1.w *= w1.w;
            uint32_t h0, l0, h1, l1, h2, l2, h3, l3;
            split2(v0.x, v0.y, h0, l0); split2(v0.z, v0.w, h1, l1);
            split2(v1.x, v1.y, h2, l2); split2(v1.z, v1.w, h3, l3);
            uint32_t off = row * 256 + ((ch ^ (row & 7)) << 4);
            *(uint4*)(smem + off)              = make_uint4(h0, h1, h2, h3);
            *(uint4*)(smem + BUF_STRIDE + off) = make_uint4(l0, l1, l2, l3);
        }
        __syncthreads();

        /* ---- prologue B: loop-invariant Q A-fragments into registers ---- */
        uint32_t aQh[8][4], aQl[8][4];
        #pragma unroll
        for (int kt = 0; kt < 8; ++kt) {
            int ach = kt * 2 + a_cs;
            uint32_t aoff = a_row * 256 + ((ach ^ (a_row & 7)) << 4);
            LDSM4(aQh[kt], sb + aoff);
            LDSM4(aQl[kt], sb + BUF_STRIDE + aoff);
        }
        __syncthreads();   /* Q reads done — buffers free for K */

        /* ---- prologue C: K tile kt0 → buf0 ---- */
        {
            const int kb = kt0 * BN;
            #pragma unroll
            for (int i = 0; i < 4; ++i) {
                int row = srow + 16 * i;
                const float* src = qst + (size_t)(kb + row) * D_DIM + sch * 8;
                float4 v0 = *(const float4*)src, v1 = *(const float4*)(src + 4);
                uint32_t h0, l0, h1, l1, h2, l2, h3, l3;
                split2(v0.x, v0.y, h0, l0); split2(v0.z, v0.w, h1, l1);
                split2(v1.x, v1.y, h2, l2); split2(v1.z, v1.w, h3, l3);
                uint32_t off = row * 256 + ((sch ^ (row & 7)) << 4);
                *(uint4*)(smem + off)              = make_uint4(h0, h1, h2, h3);
                *(uint4*)(smem + OFF_KL_REL + off) = make_uint4(l0, l1, l2, l3);
            }
            if (tid < BN) ((float*)(smem + OFF_QB))[tid] = g_qbias[kb + tid];
        }

        float O[16][4];
        float msc0 = 0.f, msc1 = 0.f;
        float l0r = 0.f, l1r = 0.f;
        float pm0 = 0.f, pm1 = 0.f;
        #pragma unroll
        for (int nt = 0; nt < 16; ++nt)
            #pragma unroll
            for (int c = 0; c < 4; ++c) O[nt][c] = 0.f;

        uint32_t P[8][2];   /* carried across tiles (deferred GEMM2) */

        for (int t = 0; t < ntl; ++t) {
            __syncthreads();   /* buf[t%3] ready; buf[(t+1)%3] free; buf[(t+2)%3] = t-1 data */
            const uint32_t bufR = sb + (uint32_t)(t % 3) * BUF_STRIDE;
            const uint32_t bufP = sb + (uint32_t)((t + 2) % 3) * BUF_STRIDE;   /* tile t-1 */
            const uint32_t bufW = (uint32_t)((t + 1) % 3) * BUF_STRIDE;
            const bool has_next = (t + 1 < ntl);
            const float* qbp = (const float*)(smem + OFF_QB + (t % 3) * 256);

            /* stage fp32 loads of K tile t+1 (latency hidden under MMA region) */
            float4 sA[4], sB[4];
            float sqb = 0.f;
            if (has_next) {
                const int kb = (kt0 + t + 1) * BN;
                #pragma unroll
                for (int i = 0; i < 4; ++i) {
                    const float* src = qst + (size_t)(kb + srow + 16 * i) * D_DIM + sch * 8;
                    sA[i] = *(const float4*)src;
                    sB[i] = *(const float4*)(src + 4);
                }
                if (tid < BN) sqb = g_qbias[kb + tid];
            }

            /* ---- GEMM1(t): S = bias + Qh*Kh + Ql*Kh + Qh*Kl ---- */
            float S[8][4];
            #pragma unroll
            for (int nt = 0; nt < 8; ++nt) {
                float2 tq = *(const float2*)&qbp[nt * 8 + (lane & 3) * 2];
                S[nt][0] = tq.x; S[nt][1] = tq.y;
                S[nt][2] = tq.x; S[nt][3] = tq.y;
            }
            #pragma unroll
            for (int kt = 0; kt < 8; ++kt) {
                uint32_t bh[4][4];
                #pragma unroll
                for (int np = 0; np < 4; ++np) {
                    int key = np * 16 + b1_key;
                    int ch  = kt * 2 + b1_cs;
                    LDSM4(bh[np], bufR + key * 256 + ((ch ^ (key & 7)) << 4));
                }
                #pragma unroll
                for (int np = 0; np < 4; ++np) {
                    MMA(S[2 * np],     aQh[kt], &bh[np][0]);
                    MMA(S[2 * np + 1], aQh[kt], &bh[np][2]);
                }
                #pragma unroll
                for (int np = 0; np < 4; ++np) {
                    MMA(S[2 * np],     aQl[kt], &bh[np][0]);
                    MMA(S[2 * np + 1], aQl[kt], &bh[np][2]);
                }
                #pragma unroll
                for (int np = 0; np < 4; ++np) {   /* reuse regs for Kl */
                    int key = np * 16 + b1_key;
                    int ch  = kt * 2 + b1_cs;
                    LDSM4(bh[np], bufR + OFF_KL_REL + key * 256 + ((ch ^ (key & 7)) << 4));
                }
                #pragma unroll
                for (int np = 0; np < 4; ++np) {
                    MMA(S[2 * np],     aQh[kt], &bh[np][0]);
                    MMA(S[2 * np + 1], aQh[kt], &bh[np][2]);
                }
            }

            /* ---- GEMM2(t-1): O += P_prev * Vh_prev (independent of GEMM1) ---- */
            if (t > 0) {
                #pragma unroll
                for (int kt2 = 0; kt2 < 4; ++kt2) {
                    uint32_t aP[4] = { P[2 * kt2][0], P[2 * kt2][1],
                                       P[2 * kt2 + 1][0], P[2 * kt2 + 1][1] };
                    const int key = kt2 * 16 + b2_key;
                    const uint32_t krow = bufP + key * 256;
                    #pragma unroll
                    for (int dp = 0; dp < 8; ++dp) {
                        uint32_t bv[4];
                        int ch = dp * 2 + b2_cs;
                        LDSM4T(bv, krow + ((ch ^ (key & 7)) << 4));
                        MMA(O[2 * dp],     aP, &bv[0]);
                        MMA(O[2 * dp + 1], aP, &bv[2]);
                    }
                }
            }

            /* ---- convert + store staged tile t+1 into the free buffer ---- */
            if (has_next) {
                #pragma unroll
                for (int i = 0; i < 4; ++i) {
                    int row = srow + 16 * i;
                    uint32_t h0, l0, h1, l1, h2, l2, h3, l3;
                    split2(sA[i].x, sA[i].y, h0, l0); split2(sA[i].z, sA[i].w, h1, l1);
                    split2(sB[i].x, sB[i].y, h2, l2); split2(sB[i].z, sB[i].w, h3, l3);
                    uint32_t off = row * 256 + ((sch ^ (row & 7)) << 4);
                    *(uint4*)(smem + bufW + off)              = make_uint4(h0, h1, h2, h3);
                    *(uint4*)(smem + bufW + OFF_KL_REL + off) = make_uint4(l0, l1, l2, l3);
                }
                if (tid < BN) ((float*)(smem + OFF_QB + ((t + 1) % 3) * 256))[tid] = sqb;
            }

            /* ---- static-scale base-2 softmax: S → P (consumed next iter) ---- */
            {
                if (t == 0) {   /* one-time static scale = row max of first tile */
                    float mx0 = -INFINITY, mx1 = -INFINITY;
                    #pragma unroll
                    for (int nt = 0; nt < 8; ++nt) {
                        mx0 = fmaxf(mx0, fmaxf(S[nt][0], S[nt][1]));
                        mx1 = fmaxf(mx1, fmaxf(S[nt][2], S[nt][3]));
                    }
                    mx0 = fmaxf(mx0, __shfl_xor_sync(0xffffffffu, mx0, 1));
                    mx0 = fmaxf(mx0, __shfl_xor_sync(0xffffffffu, mx0, 2));
                    mx1 = fmaxf(mx1, __shfl_xor_sync(0xffffffffu, mx1, 1));
                    mx1 = fmaxf(mx1, __shfl_xor_sync(0xffffffffu, mx1, 2));
                    msc0 = mx0; msc1 = mx1;
                }
                #pragma unroll
                for (int nt = 0; nt < 8; ++nt) {
                    float p0 = ex2(S[nt][0] - msc0);
                    float p1 = ex2(S[nt][1] - msc0);
                    float p2 = ex2(S[nt][2] - msc1);
                    float p3 = ex2(S[nt][3] - msc1);
                    l0r += p0 + p1;  l1r += p2 + p3;
                    pm0 = fmaxf(pm0, fmaxf(p0, p1));
                    pm1 = fmaxf(pm1, fmaxf(p2, p3));
                    P[nt][0] = pack_bf16x2(p0, p1);
                    P[nt][1] = pack_bf16x2(p2, p3);
                }
            }
        }

        /* ---- drain: GEMM2 of the final tile (buffer untouched since) ---- */
        {
            const uint32_t bufP = sb + (uint32_t)((ntl - 1) % 3) * BUF_STRIDE;
            #pragma unroll
            for (int kt2 = 0; kt2 < 4; ++kt2) {
                uint32_t aP[4] = { P[2 * kt2][0], P[2 * kt2][1],
                                   P[2 * kt2 + 1][0], P[2 * kt2 + 1][1] };
                const int key = kt2 * 16 + b2_key;
                const uint32_t krow = bufP + key * 256;
                #pragma unroll
                for (int dp = 0; dp < 8; ++dp) {
                    uint32_t bv[4];
                    int ch = dp * 2 + b2_cs;
                    LDSM4T(bv, krow + ((ch ^ (key & 7)) << 4));
                    MMA(O[2 * dp],     aP, &bv[0]);
                    MMA(O[2 * dp + 1], aP, &bv[2]);
                }
            }
        }

        /* ---- segment epilogue: reduce l/pm, write slot ---- */
        {
            l0r += __shfl_xor_sync(0xffffffffu, l0r, 1);
            l0r += __shfl_xor_sync(0xffffffffu, l0r, 2);
            l1r += __shfl_xor_sync(0xffffffffu, l1r, 1);
            l1r += __shfl_xor_sync(0xffffffffu, l1r, 2);
            pm0 = fmaxf(pm0, __shfl_xor_sync(0xffffffffu, pm0, 1));
            pm0 = fmaxf(pm0, __shfl_xor_sync(0xffffffffu, pm0, 2));
            pm1 = fmaxf(pm1, __shfl_xor_sync(0xffffffffu, pm1, 1));
            pm1 = fmaxf(pm1, __shfl_xor_sync(0xffffffffu, pm1, 2));

            int r1 = row0 + m0 + (lane >> 2);
            int r2 = r1 + 8;
            if ((lane & 3) == 0) {
                g_ml[(size_t)slot * T_DIM + r1] = make_float4(msc0, pm0, l0r, 0.f);
                g_ml[(size_t)slot * T_DIM + r2] = make_float4(msc1, pm1, l1r, 0.f);
            }
            float* o1 = g_O + ((size_t)slot * T_DIM + r1) * D_DIM + (lane & 3) * 2;
            float* o2 = g_O + ((size_t)slot * T_DIM + r2) * D_DIM + (lane & 3) * 2;
            #pragma unroll
            for (int nt = 0; nt < 16; ++nt) {
                *(float2*)(o1 + nt * 8) = make_float2(O[nt][0], O[nt][1]);
                *(float2*)(o2 + nt * 8) = make_float2(O[nt][2], O[nt][3]);
            }
        }
        ft = tend;
    }
}

/* ============ K2: combine slots, write out cols [0,384), emit b, h partials ============ */
__global__ void combine_kernel(const float* __restrict__ x, float* __restrict__ out) {
    __shared__ float stage[8 * 128];
    int row  = blockIdx.x * 8 + (threadIdx.x >> 5);
    int warp = threadIdx.x >> 5;
    int lane = threadIdx.x & 31;
    float4 ml[4];
    float M = -INFINITY;
    #pragma unroll
    for (int s = 0; s < 4; ++s) {
        ml[s] = g_ml[(size_t)s * T_DIM + row];
        if (ml[s].z != 0.f) M = fmaxf(M, ml[s].x);
    }
    float L = 0.f, bmax = 0.f;
    float4 U = make_float4(0.f, 0.f, 0.f, 0.f);
    #pragma unroll
    for (int s = 0; s < 4; ++s) {
        if (ml[s].z != 0.f) {          /* warp-uniform branch */
            float e = ex2(ml[s].x - M);
            L += ml[s].z * e;
            bmax = fmaxf(bmax, ml[s].y * e);
            float4 o = *(const float4*)&g_O[((size_t)s * T_DIM + row) * D_DIM + lane * 4];
            U.x += o.x * e; U.y += o.y * e; U.z += o.z * e; U.w += o.w * e;
        }
    }
    float invL = 1.0f / L;
    U.x *= invL; U.y *= invL; U.z *= invL; U.w *= invL;
    float4 c = *(const float4*)&x[(size_t)row * D_DIM + lane * 4];
    float* orow = out + (size_t)row * (4 * D_DIM);
    *(float4*)&orow[lane * 4]             = c;
    *(float4*)&orow[D_DIM + lane * 4]     = U;
    *(float4*)&orow[2 * D_DIM + lane * 4] = make_float4(c.x * U.x, c.y * U.y, c.z * U.z, c.w * U.w);
    float b = bmax * invL;                 /* lane-uniform */
    if (lane == 0) g_b[row] = b;
    /* h partial: this block's 8 rows */
    *(float4*)&stage[warp * 128 + lane * 4] = make_float4(b * c.x, b * c.y, b * c.z, b * c.w);
    __syncthreads();
    if (threadIdx.x < 128) {
        float s = 0.f;
        #pragma unroll
        for (int ww = 0; ww < 8; ++ww) s += stage[ww * 128 + threadIdx.x];
        g_hpart[blockIdx.x * 128 + threadIdx.x] = s;
    }
}

/* ============ K3a/K3b: two-stage deterministic h reduction ============ */
__global__ void hreduce1_kernel() {
    int d = threadIdx.x;
    int b0 = blockIdx.x * 16;
    float s = 0.f;
    #pragma unroll
    for (int i = 0; i < 16; ++i) s += g_hpart[(size_t)(b0 + i) * 128 + d];
    g_h2[blockIdx.x * 128 + d] = s;
}
__global__ void hreduce2_kernel() {
    int d = threadIdx.x;
    float s = 0.f;
    #pragma unroll
    for (int b = 0; b < 64; ++b) s += g_h2[b * 128 + d];
    g_h[d] = s;
}
__global__ void hwrite_kernel(const float* __restrict__ x, float* __restrict__ out) {
    int idx = blockIdx.x * blockDim.x + threadIdx.x;
    int row = idx >> 5;
    int dq  = idx & 31;
    float4 c = ((const float4*)x)[(size_t)row * 32 + dq];
    float4 h = ((const float4*)g_h)[dq];
    ((float4*)out)[(size_t)row * 128 + 96 + dq] =
        make_float4(c.x * h.x, c.y * h.y, c.z * h.z, c.w * h.w);
}

/* ============================================================================ */
extern "C" void kernel_launch(void* const* d_in, const int* in_sizes, int n_in,
                              void* d_out, int out_size) {
    const float* x    = (const float*)d_in[0];
    const float* kern = (const float*)d_in[1];
    float* out = (float*)d_out;

    cudaFuncSetAttribute(flash_kernel, cudaFuncAttributeMaxDynamicSharedMemorySize, SMEM_SZ);

    qbias_kernel<<<T_DIM / 8, 256>>>(x, kern);
    flash_kernel<<<NCTA, NTH, SMEM_SZ>>>(x, kern);
    combine_kernel<<<T_DIM / 8, 256>>>(x, out);
    hreduce1_kernel<<<64, 128>>>();
    hreduce2_kernel<<<1, 128>>>();
    hwrite_kernel<<<(T_DIM * D_DIM / 4) / 256, 256>>>(x, out);
}

// round 14
// speedup vs baseline: 1.0339x; 1.0339x over previous
#include <cuda_runtime.h>
#include <cuda_bf16.h>
#include <math.h>
#include <stdint.h>

#define T_DIM 8192
#define D_DIM 128
#define BM 128
#define BN 64
#define NTH 256
#define NCTA 148
#define FT_TOTAL 8192            /* 64 rowblocks * 128 keytiles */
#define LOG2E 1.4426950408889634f

/* smem: two 32KB K buffers (KH 16K | KL 16K) + qbias double buffer */
#define BUF_STRIDE 32768
#define OFF_KL_REL 16384
#define OFF_QB 65536
#define SMEM_SZ 66048

__device__ float  g_qbias[T_DIM];
__device__ float  g_O[4 * T_DIM * D_DIM];     /* 4 slots; unwritten stay 0 */
__device__ float4 g_ml[4 * T_DIM];            /* (m_scale, p_max, l, 0)    */
__device__ float  g_b[T_DIM];
__device__ float  g_hpart[1024 * D_DIM];
__device__ float  g_h2[64 * D_DIM];
__device__ float  g_h[D_DIM];

__device__ __forceinline__ uint32_t smem_u32(const void* p) {
    uint32_t a;
    asm("{ .reg .u64 t; cvta.to.shared.u64 t, %1; cvt.u32.u64 %0, t; }" : "=r"(a) : "l"(p));
    return a;
}
__device__ __forceinline__ float ex2(float x) {
    float y;
    asm("ex2.approx.f32 %0, %1;" : "=f"(y) : "f"(x));
    return y;
}
__device__ __forceinline__ uint32_t pack_bf16x2(float lo, float hi) {
    uint32_t r;
    asm("cvt.rn.bf16x2.f32 %0, %1, %2;" : "=r"(r) : "f"(hi), "f"(lo));
    return r;
}
__device__ __forceinline__ void split2(float a, float b, uint32_t& hi, uint32_t& lo) {
    hi = pack_bf16x2(a, b);
    float fa = __uint_as_float(hi << 16);
    float fb = __uint_as_float(hi & 0xffff0000u);
    lo = pack_bf16x2(a - fa, b - fb);
}

#define LDSM4(r, addr) \
    asm volatile("ldmatrix.sync.aligned.m8n8.x4.shared.b16 {%0,%1,%2,%3}, [%4];" \
        : "=r"((r)[0]), "=r"((r)[1]), "=r"((r)[2]), "=r"((r)[3]) : "r"(addr))
#define LDSM4T(r, addr) \
    asm volatile("ldmatrix.sync.aligned.m8n8.x4.trans.shared.b16 {%0,%1,%2,%3}, [%4];" \
        : "=r"((r)[0]), "=r"((r)[1]), "=r"((r)[2]), "=r"((r)[3]) : "r"(addr))
#define MMA(c, a, b) \
    asm volatile("mma.sync.aligned.m16n8k16.row.col.f32.bf16.bf16.f32 " \
        "{%0,%1,%2,%3}, {%4,%5,%6,%7}, {%8,%9}, {%0,%1,%2,%3};" \
        : "+f"((c)[0]), "+f"((c)[1]), "+f"((c)[2]), "+f"((c)[3]) \
        : "r"((a)[0]), "r"((a)[1]), "r"((a)[2]), "r"((a)[3]), "r"((b)[0]), "r"((b)[1]))

/* ================= K0: qbias[j] = (question[j] . w_q) * log2(e) ================= */
__global__ void qbias_kernel(const float* __restrict__ x, const float* __restrict__ kern) {
    int j = blockIdx.x * 8 + (threadIdx.x >> 5);
    int lane = threadIdx.x & 31;
    const float* q  = x + (size_t)T_DIM * D_DIM + (size_t)j * D_DIM;
    const float* wq = kern + D_DIM;
    float s = q[lane] * wq[lane] + q[lane + 32] * wq[lane + 32]
            + q[lane + 64] * wq[lane + 64] + q[lane + 96] * wq[lane + 96];
    #pragma unroll
    for (int off = 16; off; off >>= 1) s += __shfl_xor_sync(0xffffffffu, s, off);
    if (lane == 0) g_qbias[j] = s * LOG2E;
}

/* ================= K1: HMMA flash, interleaved conv/softmax hiding ================= */
__global__ void __launch_bounds__(NTH, 1)
flash_kernel(const float* __restrict__ x, const float* __restrict__ kern)
{
    extern __shared__ char smem[];
    const uint32_t sb = smem_u32(smem);

    const int tid  = threadIdx.x;
    const int lane = tid & 31;
    const int w    = tid >> 5;
    const int cta  = blockIdx.x;
    const int ft0  = (FT_TOTAL * cta) / NCTA;
    const int ft1  = (FT_TOTAL * (cta + 1)) / NCTA;
    const int slot = cta & 3;

    const float* ctx = x;
    const float* qst = x + (size_t)T_DIM * D_DIM;
    const float* wm  = kern + 2 * D_DIM;

    const int m0 = w * 16;
    const int a_row = m0 + (lane & 15);
    const int a_cs  = (lane >> 4);
    const int b1_key = ((lane >> 4) << 3) + (lane & 7);
    const int b1_cs  = ((lane >> 3) & 1);
    const int b2_key = ((lane >> 3) & 1) * 8 + (lane & 7);
    const int b2_cs  = (lane >> 4);
    const int srow = tid >> 4, sch = tid & 15;

    int ft = ft0;
    while (ft < ft1) {
        const int ra   = ft >> 7;
        const int tend = min(ft1, (ra + 1) << 7);
        const int kt0  = ft & 127;
        const int ntl  = tend - ft;
        const int row0 = ra * BM;

        __syncthreads();   /* prior segment's smem reads complete */

        /* ---- prologue A: Q' = ctx*w_m*log2e → bf16 hi/lo staged in bufs 0/1 ---- */
        #pragma unroll
        for (int i = 0; i < 8; ++i) {
            int idx = tid + i * NTH;
            int row = idx >> 4, ch = idx & 15;
            const float* src = ctx + (size_t)(row0 + row) * D_DIM + ch * 8;
            float4 v0 = *(const float4*)src, v1 = *(const float4*)(src + 4);
            float4 w0 = *(const float4*)&wm[ch * 8], w1 = *(const float4*)&wm[ch * 8 + 4];
            w0.x *= LOG2E; w0.y *= LOG2E; w0.z *= LOG2E; w0.w *= LOG2E;
            w1.x *= LOG2E; w1.y *= LOG2E; w1.z *= LOG2E; w1.w *= LOG2E;
            v0.x *= w0.x; v0.y *= w0.y; v0.z *= w0.z; v0.w *= w0.w;
            v1.x *= w1.x; v1.y *= w1.y; v1.z *= w1.z; v1.w *= w1.w;
            uint32_t h0, l0, h1, l1, h2, l2, h3, l3;
            split2(v0.x, v0.y, h0, l0); split2(v0.z, v0.w, h1, l1);
            split2(v1.x, v1.y, h2, l2); split2(v1.z, v1.w, h3, l3);
            uint32_t off = row * 256 + ((ch ^ (row & 7)) << 4);
            *(uint4*)(smem + off)              = make_uint4(h0, h1, h2, h3);
            *(uint4*)(smem + BUF_STRIDE + off) = make_uint4(l0, l1, l2, l3);
        }
        __syncthreads();

        /* ---- prologue B: loop-invariant Q A-fragments into registers ---- */
        uint32_t aQh[8][4], aQl[8][4];
        #pragma unroll
        for (int kt = 0; kt < 8; ++kt) {
            int ach = kt * 2 + a_cs;
            uint32_t aoff = a_row * 256 + ((ach ^ (a_row & 7)) << 4);
            LDSM4(aQh[kt], sb + aoff);
            LDSM4(aQl[kt], sb + BUF_STRIDE + aoff);
        }
        __syncthreads();   /* Q reads done — buffers free for K */

        /* ---- prologue C: K tile kt0 → buf0 ---- */
        {
            const int kb = kt0 * BN;
            #pragma unroll
            for (int i = 0; i < 4; ++i) {
                int row = srow + 16 * i;
                const float* src = qst + (size_t)(kb + row) * D_DIM + sch * 8;
                float4 v0 = *(const float4*)src, v1 = *(const float4*)(src + 4);
                uint32_t h0, l0, h1, l1, h2, l2, h3, l3;
                split2(v0.x, v0.y, h0, l0); split2(v0.z, v0.w, h1, l1);
                split2(v1.x, v1.y, h2, l2); split2(v1.z, v1.w, h3, l3);
                uint32_t off = row * 256 + ((sch ^ (row & 7)) << 4);
                *(uint4*)(smem + off)              = make_uint4(h0, h1, h2, h3);
                *(uint4*)(smem + OFF_KL_REL + off) = make_uint4(l0, l1, l2, l3);
            }
            if (tid < BN) ((float*)(smem + OFF_QB))[tid] = g_qbias[kb + tid];
        }

        float O[16][4];
        float msc0 = 0.f, msc1 = 0.f;
        float l0r = 0.f, l1r = 0.f;
        float pm0 = 0.f, pm1 = 0.f;
        #pragma unroll
        for (int nt = 0; nt < 16; ++nt)
            #pragma unroll
            for (int c = 0; c < 4; ++c) O[nt][c] = 0.f;

        for (int t = 0; t < ntl; ++t) {
            __syncthreads();   /* buf[t&1] ready; buf[(t+1)&1] free */
            const uint32_t bufR = sb + (uint32_t)(t & 1) * BUF_STRIDE;
            const uint32_t bufW = (uint32_t)((t + 1) & 1) * BUF_STRIDE;
            const bool has_next = (t + 1 < ntl);
            const float* qbp = (const float*)(smem + OFF_QB + (t & 1) * 256);

            /* stage fp32 loads of K tile t+1 (latency hidden under GEMM1) */
            float4 sA[4], sB[4];
            float sqb = 0.f;
            if (has_next) {
                const int kb = (kt0 + t + 1) * BN;
                #pragma unroll
                for (int i = 0; i < 4; ++i) {
                    const float* src = qst + (size_t)(kb + srow + 16 * i) * D_DIM + sch * 8;
                    sA[i] = *(const float4*)src;
                    sB[i] = *(const float4*)(src + 4);
                }
                if (tid < BN) sqb = g_qbias[kb + tid];
            }

            /* ---- GEMM1 + conv-store interleave (8 indep S accumulators) ---- */
            float S[8][4];
            #pragma unroll
            for (int nt = 0; nt < 8; ++nt) {
                float2 tq = *(const float2*)&qbp[nt * 8 + (lane & 3) * 2];
                S[nt][0] = tq.x; S[nt][1] = tq.y;
                S[nt][2] = tq.x; S[nt][3] = tq.y;
            }
            #pragma unroll
            for (int kt = 0; kt < 8; ++kt) {
                uint32_t bh[4][4];
                #pragma unroll
                for (int np = 0; np < 4; ++np) {
                    int key = np * 16 + b1_key;
                    int ch  = kt * 2 + b1_cs;
                    LDSM4(bh[np], bufR + key * 256 + ((ch ^ (key & 7)) << 4));
                }
                #pragma unroll
                for (int np = 0; np < 4; ++np) {
                    MMA(S[2 * np],     aQh[kt], &bh[np][0]);
                    MMA(S[2 * np + 1], aQh[kt], &bh[np][2]);
                }
                #pragma unroll
                for (int np = 0; np < 4; ++np) {
                    MMA(S[2 * np],     aQl[kt], &bh[np][0]);
                    MMA(S[2 * np + 1], aQl[kt], &bh[np][2]);
                }
                #pragma unroll
                for (int np = 0; np < 4; ++np) {   /* reuse regs for Kl */
                    int key = np * 16 + b1_key;
                    int ch  = kt * 2 + b1_cs;
                    LDSM4(bh[np], bufR + OFF_KL_REL + key * 256 + ((ch ^ (key & 7)) << 4));
                }
                #pragma unroll
                for (int np = 0; np < 4; ++np) {
                    MMA(S[2 * np],     aQh[kt], &bh[np][0]);
                    MMA(S[2 * np + 1], aQh[kt], &bh[np][2]);
                }
                /* hide conversion of next tile's chunk under the MMA burst */
                if (has_next && (kt & 1)) {
                    const int i = kt >> 1;
                    int row = srow + 16 * i;
                    uint32_t h0, l0, h1, l1, h2, l2, h3, l3;
                    split2(sA[i].x, sA[i].y, h0, l0); split2(sA[i].z, sA[i].w, h1, l1);
                    split2(sB[i].x, sB[i].y, h2, l2); split2(sB[i].z, sB[i].w, h3, l3);
                    uint32_t off = row * 256 + ((sch ^ (row & 7)) << 4);
                    *(uint4*)(smem + bufW + off)              = make_uint4(h0, h1, h2, h3);
                    *(uint4*)(smem + bufW + OFF_KL_REL + off) = make_uint4(l0, l1, l2, l3);
                }
            }
            if (has_next && tid < BN)
                ((float*)(smem + OFF_QB + ((t + 1) & 1) * 256))[tid] = sqb;

            /* ---- one-time static scale (full S needed) ---- */
            if (t == 0) {
                float mx0 = -INFINITY, mx1 = -INFINITY;
                #pragma unroll
                for (int nt = 0; nt < 8; ++nt) {
                    mx0 = fmaxf(mx0, fmaxf(S[nt][0], S[nt][1]));
                    mx1 = fmaxf(mx1, fmaxf(S[nt][2], S[nt][3]));
                }
                mx0 = fmaxf(mx0, __shfl_xor_sync(0xffffffffu, mx0, 1));
                mx0 = fmaxf(mx0, __shfl_xor_sync(0xffffffffu, mx0, 2));
                mx1 = fmaxf(mx1, __shfl_xor_sync(0xffffffffu, mx1, 1));
                mx1 = fmaxf(mx1, __shfl_xor_sync(0xffffffffu, mx1, 2));
                msc0 = mx0; msc1 = mx1;
            }

            /* ---- fused softmax-chunk + GEMM2 per 16-key group ---- */
            #pragma unroll
            for (int kt2 = 0; kt2 < 4; ++kt2) {
                uint32_t aP[4];
                {
                    float p0 = ex2(S[2 * kt2][0] - msc0);
                    float p1 = ex2(S[2 * kt2][1] - msc0);
                    float p2 = ex2(S[2 * kt2][2] - msc1);
                    float p3 = ex2(S[2 * kt2][3] - msc1);
                    float p4 = ex2(S[2 * kt2 + 1][0] - msc0);
                    float p5 = ex2(S[2 * kt2 + 1][1] - msc0);
                    float p6 = ex2(S[2 * kt2 + 1][2] - msc1);
                    float p7 = ex2(S[2 * kt2 + 1][3] - msc1);
                    l0r += (p0 + p1) + (p4 + p5);
                    l1r += (p2 + p3) + (p6 + p7);
                    pm0 = fmaxf(pm0, fmaxf(fmaxf(p0, p1), fmaxf(p4, p5)));
                    pm1 = fmaxf(pm1, fmaxf(fmaxf(p2, p3), fmaxf(p6, p7)));
                    aP[0] = pack_bf16x2(p0, p1);
                    aP[1] = pack_bf16x2(p2, p3);
                    aP[2] = pack_bf16x2(p4, p5);
                    aP[3] = pack_bf16x2(p6, p7);
                }
                const int key = kt2 * 16 + b2_key;
                const uint32_t krow = bufR + key * 256;
                #pragma unroll
                for (int dp = 0; dp < 8; ++dp) {
                    uint32_t bv[4];
                    int ch = dp * 2 + b2_cs;
                    LDSM4T(bv, krow + ((ch ^ (key & 7)) << 4));
                    MMA(O[2 * dp],     aP, &bv[0]);
                    MMA(O[2 * dp + 1], aP, &bv[2]);
                }
            }
        }

        /* ---- segment epilogue: reduce l/pm, write slot ---- */
        {
            l0r += __shfl_xor_sync(0xffffffffu, l0r, 1);
            l0r += __shfl_xor_sync(0xffffffffu, l0r, 2);
            l1r += __shfl_xor_sync(0xffffffffu, l1r, 1);
            l1r += __shfl_xor_sync(0xffffffffu, l1r, 2);
            pm0 = fmaxf(pm0, __shfl_xor_sync(0xffffffffu, pm0, 1));
            pm0 = fmaxf(pm0, __shfl_xor_sync(0xffffffffu, pm0, 2));
            pm1 = fmaxf(pm1, __shfl_xor_sync(0xffffffffu, pm1, 1));
            pm1 = fmaxf(pm1, __shfl_xor_sync(0xffffffffu, pm1, 2));

            int r1 = row0 + m0 + (lane >> 2);
            int r2 = r1 + 8;
            if ((lane & 3) == 0) {
                g_ml[(size_t)slot * T_DIM + r1] = make_float4(msc0, pm0, l0r, 0.f);
                g_ml[(size_t)slot * T_DIM + r2] = make_float4(msc1, pm1, l1r, 0.f);
            }
            float* o1 = g_O + ((size_t)slot * T_DIM + r1) * D_DIM + (lane & 3) * 2;
            float* o2 = g_O + ((size_t)slot * T_DIM + r2) * D_DIM + (lane & 3) * 2;
            #pragma unroll
            for (int nt = 0; nt < 16; ++nt) {
                *(float2*)(o1 + nt * 8) = make_float2(O[nt][0], O[nt][1]);
                *(float2*)(o2 + nt * 8) = make_float2(O[nt][2], O[nt][3]);
            }
        }
        ft = tend;
    }
}

/* ============ K2: combine slots, write out cols [0,384), emit b, h partials ============ */
__global__ void combine_kernel(const float* __restrict__ x, float* __restrict__ out) {
    __shared__ float stage[8 * 128];
    int row  = blockIdx.x * 8 + (threadIdx.x >> 5);
    int warp = threadIdx.x >> 5;
    int lane = threadIdx.x & 31;
    float4 ml[4];
    float M = -INFINITY;
    #pragma unroll
    for (int s = 0; s < 4; ++s) {
        ml[s] = g_ml[(size_t)s * T_DIM + row];
        if (ml[s].z != 0.f) M = fmaxf(M, ml[s].x);
    }
    float L = 0.f, bmax = 0.f;
    float4 U = make_float4(0.f, 0.f, 0.f, 0.f);
    #pragma unroll
    for (int s = 0; s < 4; ++s) {
        if (ml[s].z != 0.f) {          /* warp-uniform branch */
            float e = ex2(ml[s].x - M);
            L += ml[s].z * e;
            bmax = fmaxf(bmax, ml[s].y * e);
            float4 o = *(const float4*)&g_O[((size_t)s * T_DIM + row) * D_DIM + lane * 4];
            U.x += o.x * e; U.y += o.y * e; U.z += o.z * e; U.w += o.w * e;
        }
    }
    float invL = 1.0f / L;
    U.x *= invL; U.y *= invL; U.z *= invL; U.w *= invL;
    float4 c = *(const float4*)&x[(size_t)row * D_DIM + lane * 4];
    float* orow = out + (size_t)row * (4 * D_DIM);
    *(float4*)&orow[lane * 4]             = c;
    *(float4*)&orow[D_DIM + lane * 4]     = U;
    *(float4*)&orow[2 * D_DIM + lane * 4] = make_float4(c.x * U.x, c.y * U.y, c.z * U.z, c.w * U.w);
    float b = bmax * invL;                 /* lane-uniform */
    if (lane == 0) g_b[row] = b;
    /* h partial: this block's 8 rows */
    *(float4*)&stage[warp * 128 + lane * 4] = make_float4(b * c.x, b * c.y, b * c.z, b * c.w);
    __syncthreads();
    if (threadIdx.x < 128) {
        float s = 0.f;
        #pragma unroll
        for (int ww = 0; ww < 8; ++ww) s += stage[ww * 128 + threadIdx.x];
        g_hpart[blockIdx.x * 128 + threadIdx.x] = s;
    }
}

/* ============ K3a/K3b: two-stage deterministic h reduction ============ */
__global__ void hreduce1_kernel() {
    int d = threadIdx.x;
    int b0 = blockIdx.x * 16;
    float s = 0.f;
    #pragma unroll
    for (int i = 0; i < 16; ++i) s += g_hpart[(size_t)(b0 + i) * 128 + d];
    g_h2[blockIdx.x * 128 + d] = s;
}
__global__ void hreduce2_kernel() {
    int d = threadIdx.x;
    float s = 0.f;
    #pragma unroll
    for (int b = 0; b < 64; ++b) s += g_h2[b * 128 + d];
    g_h[d] = s;
}
__global__ void hwrite_kernel(const float* __restrict__ x, float* __restrict__ out) {
    int idx = blockIdx.x * blockDim.x + threadIdx.x;
    int row = idx >> 5;
    int dq  = idx & 31;
    float4 c = ((const float4*)x)[(size_t)row * 32 + dq];
    float4 h = ((const float4*)g_h)[dq];
    ((float4*)out)[(size_t)row * 128 + 96 + dq] =
        make_float4(c.x * h.x, c.y * h.y, c.z * h.z, c.w * h.w);
}

/* ============================================================================ */
extern "C" void kernel_launch(void* const* d_in, const int* in_sizes, int n_in,
                              void* d_out, int out_size) {
    const float* x    = (const float*)d_in[0];
    const float* kern = (const float*)d_in[1];
    float* out = (float*)d_out;

    cudaFuncSetAttribute(flash_kernel, cudaFuncAttributeMaxDynamicSharedMemorySize, SMEM_SZ);

    qbias_kernel<<<T_DIM / 8, 256>>>(x, kern);
    flash_kernel<<<NCTA, NTH, SMEM_SZ>>>(x, kern);
    combine_kernel<<<T_DIM / 8, 256>>>(x, out);
    hreduce1_kernel<<<64, 128>>>();
    hreduce2_kernel<<<1, 128>>>();
    hwrite_kernel<<<(T_DIM * D_DIM / 4) / 256, 256>>>(x, out);
}

// round 15
// speedup vs baseline: 1.0586x; 1.0238x over previous
#include <cuda_runtime.h>
#include <cuda_bf16.h>
#include <math.h>
#include <stdint.h>

#define T_DIM 8192
#define D_DIM 128
#define BM 128
#define BN 64
#define NTH 256
#define NCTA 148
#define FT_TOTAL 8192            /* 64 rowblocks * 128 keytiles */
#define LOG2E 1.4426950408889634f

/* smem: FOUR 32KB K buffers (KH 16K | KL 16K) + qbias quad buffer */
#define BUF_STRIDE 32768
#define OFF_KL_REL 16384
#define OFF_QB (4 * BUF_STRIDE)            /* 131072 */
#define SMEM_SZ (OFF_QB + 4 * 256 + 128)   /* 132224 */

__device__ float  g_qbias[T_DIM];
__device__ float  g_O[4 * T_DIM * D_DIM];     /* 4 slots; unwritten stay 0 */
__device__ float4 g_ml[4 * T_DIM];            /* (m_scale, p_max, l, 0)    */
__device__ float  g_b[T_DIM];
__device__ float  g_hpart[1024 * D_DIM];
__device__ float  g_h2[64 * D_DIM];
__device__ float  g_h[D_DIM];

__device__ __forceinline__ uint32_t smem_u32(const void* p) {
    uint32_t a;
    asm("{ .reg .u64 t; cvta.to.shared.u64 t, %1; cvt.u32.u64 %0, t; }" : "=r"(a) : "l"(p));
    return a;
}
__device__ __forceinline__ float ex2(float x) {
    float y;
    asm("ex2.approx.f32 %0, %1;" : "=f"(y) : "f"(x));
    return y;
}
__device__ __forceinline__ uint32_t pack_bf16x2(float lo, float hi) {
    uint32_t r;
    asm("cvt.rn.bf16x2.f32 %0, %1, %2;" : "=r"(r) : "f"(hi), "f"(lo));
    return r;
}
__device__ __forceinline__ void split2(float a, float b, uint32_t& hi, uint32_t& lo) {
    hi = pack_bf16x2(a, b);
    float fa = __uint_as_float(hi << 16);
    float fb = __uint_as_float(hi & 0xffff0000u);
    lo = pack_bf16x2(a - fa, b - fb);
}

#define LDSM4(r, addr) \
    asm volatile("ldmatrix.sync.aligned.m8n8.x4.shared.b16 {%0,%1,%2,%3}, [%4];" \
        : "=r"((r)[0]), "=r"((r)[1]), "=r"((r)[2]), "=r"((r)[3]) : "r"(addr))
#define LDSM4T(r, addr) \
    asm volatile("ldmatrix.sync.aligned.m8n8.x4.trans.shared.b16 {%0,%1,%2,%3}, [%4];" \
        : "=r"((r)[0]), "=r"((r)[1]), "=r"((r)[2]), "=r"((r)[3]) : "r"(addr))
#define MMA(c, a, b) \
    asm volatile("mma.sync.aligned.m16n8k16.row.col.f32.bf16.bf16.f32 " \
        "{%0,%1,%2,%3}, {%4,%5,%6,%7}, {%8,%9}, {%0,%1,%2,%3};" \
        : "+f"((c)[0]), "+f"((c)[1]), "+f"((c)[2]), "+f"((c)[3]) \
        : "r"((a)[0]), "r"((a)[1]), "r"((a)[2]), "r"((a)[3]), "r"((b)[0]), "r"((b)[1]))

/* ================= K0: qbias[j] = (question[j] . w_q) * log2(e) ================= */
__global__ void qbias_kernel(const float* __restrict__ x, const float* __restrict__ kern) {
    int j = blockIdx.x * 8 + (threadIdx.x >> 5);
    int lane = threadIdx.x & 31;
    const float* q  = x + (size_t)T_DIM * D_DIM + (size_t)j * D_DIM;
    const float* wq = kern + D_DIM;
    float s = q[lane] * wq[lane] + q[lane + 32] * wq[lane + 32]
            + q[lane + 64] * wq[lane + 64] + q[lane + 96] * wq[lane + 96];
    #pragma unroll
    for (int off = 16; off; off >>= 1) s += __shfl_xor_sync(0xffffffffu, s, off);
    if (lane == 0) g_qbias[j] = s * LOG2E;
}

/* ================= K1: HMMA flash, 4-buffer ring, sync every 2 tiles ================= */
__global__ void __launch_bounds__(NTH, 1)
flash_kernel(const float* __restrict__ x, const float* __restrict__ kern)
{
    extern __shared__ char smem[];
    const uint32_t sb = smem_u32(smem);

    const int tid  = threadIdx.x;
    const int lane = tid & 31;
    const int w    = tid >> 5;
    const int cta  = blockIdx.x;
    const int ft0  = (FT_TOTAL * cta) / NCTA;
    const int ft1  = (FT_TOTAL * (cta + 1)) / NCTA;
    const int slot = cta & 3;

    const float* ctx = x;
    const float* qst = x + (size_t)T_DIM * D_DIM;
    const float* wm  = kern + 2 * D_DIM;

    const int m0 = w * 16;
    const int a_row = m0 + (lane & 15);
    const int a_cs  = (lane >> 4);
    const int b1_key = ((lane >> 4) << 3) + (lane & 7);
    const int b1_cs  = ((lane >> 3) & 1);
    const int b2_key = ((lane >> 3) & 1) * 8 + (lane & 7);
    const int b2_cs  = (lane >> 4);
    const int srow = tid >> 4, sch = tid & 15;

    int ft = ft0;
    while (ft < ft1) {
        const int ra   = ft >> 7;
        const int tend = min(ft1, (ra + 1) << 7);
        const int kt0  = ft & 127;
        const int ntl  = tend - ft;
        const int row0 = ra * BM;

        __syncthreads();   /* prior segment's smem reads complete */

        /* ---- prologue A: Q' = ctx*w_m*log2e → bf16 hi/lo staged in bufs 0/1 ---- */
        #pragma unroll
        for (int i = 0; i < 8; ++i) {
            int idx = tid + i * NTH;
            int row = idx >> 4, ch = idx & 15;
            const float* src = ctx + (size_t)(row0 + row) * D_DIM + ch * 8;
            float4 v0 = *(const float4*)src, v1 = *(const float4*)(src + 4);
            float4 w0 = *(const float4*)&wm[ch * 8], w1 = *(const float4*)&wm[ch * 8 + 4];
            w0.x *= LOG2E; w0.y *= LOG2E; w0.z *= LOG2E; w0.w *= LOG2E;
            w1.x *= LOG2E; w1.y *= LOG2E; w1.z *= LOG2E; w1.w *= LOG2E;
            v0.x *= w0.x; v0.y *= w0.y; v0.z *= w0.z; v0.w *= w0.w;
            v1.x *= w1.x; v1.y *= w1.y; v1.z *= w1.z; v1.w *= w1.w;
            uint32_t h0, l0, h1, l1, h2, l2, h3, l3;
            split2(v0.x, v0.y, h0, l0); split2(v0.z, v0.w, h1, l1);
            split2(v1.x, v1.y, h2, l2); split2(v1.z, v1.w, h3, l3);
            uint32_t off = row * 256 + ((ch ^ (row & 7)) << 4);
            *(uint4*)(smem + off)              = make_uint4(h0, h1, h2, h3);
            *(uint4*)(smem + BUF_STRIDE + off) = make_uint4(l0, l1, l2, l3);
        }
        __syncthreads();

        /* ---- prologue B: loop-invariant Q A-fragments into registers ---- */
        uint32_t aQh[8][4], aQl[8][4];
        #pragma unroll
        for (int kt = 0; kt < 8; ++kt) {
            int ach = kt * 2 + a_cs;
            uint32_t aoff = a_row * 256 + ((ach ^ (a_row & 7)) << 4);
            LDSM4(aQh[kt], sb + aoff);
            LDSM4(aQl[kt], sb + BUF_STRIDE + aoff);
        }
        __syncthreads();   /* Q reads done — buffers free for K */

        /* ---- prologue C: K tiles kt0 → buf0 and kt0+1 → buf1 ---- */
        #pragma unroll
        for (int pt = 0; pt < 2; ++pt) {
            if (pt < ntl) {
                const int kb = (kt0 + pt) * BN;
                char* bufb = smem + pt * BUF_STRIDE;
                #pragma unroll
                for (int i = 0; i < 4; ++i) {
                    int row = srow + 16 * i;
                    const float* src = qst + (size_t)(kb + row) * D_DIM + sch * 8;
                    float4 v0 = *(const float4*)src, v1 = *(const float4*)(src + 4);
                    uint32_t h0, l0, h1, l1, h2, l2, h3, l3;
                    split2(v0.x, v0.y, h0, l0); split2(v0.z, v0.w, h1, l1);
                    split2(v1.x, v1.y, h2, l2); split2(v1.z, v1.w, h3, l3);
                    uint32_t off = row * 256 + ((sch ^ (row & 7)) << 4);
                    *(uint4*)(bufb + off)              = make_uint4(h0, h1, h2, h3);
                    *(uint4*)(bufb + OFF_KL_REL + off) = make_uint4(l0, l1, l2, l3);
                }
                if (tid < BN) ((float*)(smem + OFF_QB + pt * 256))[tid] = g_qbias[kb + tid];
            }
        }

        float O[16][4];
        float msc0 = 0.f, msc1 = 0.f;
        float l0r = 0.f, l1r = 0.f;
        float pm0 = 0.f, pm1 = 0.f;
        #pragma unroll
        for (int nt = 0; nt < 16; ++nt)
            #pragma unroll
            for (int c = 0; c < 4; ++c) O[nt][c] = 0.f;

        for (int t = 0; t < ntl; ++t) {
            if ((t & 1) == 0) __syncthreads();   /* bufs {t,t+1}%4 ready; {t+2,t+3}%4 free */
            const uint32_t bufR = sb + (uint32_t)(t & 3) * BUF_STRIDE;
            const uint32_t bufW = (uint32_t)((t + 2) & 3) * BUF_STRIDE;
            const bool has_next = (t + 2 < ntl);
            const float* qbp = (const float*)(smem + OFF_QB + (t & 3) * 256);

            /* stage fp32 loads of K tile t+2 (deep prefetch, hidden under GEMM1) */
            float4 sA[4], sB[4];
            float sqb = 0.f;
            if (has_next) {
                const int kb = (kt0 + t + 2) * BN;
                #pragma unroll
                for (int i = 0; i < 4; ++i) {
                    const float* src = qst + (size_t)(kb + srow + 16 * i) * D_DIM + sch * 8;
                    sA[i] = *(const float4*)src;
                    sB[i] = *(const float4*)(src + 4);
                }
                if (tid < BN) sqb = g_qbias[kb + tid];
            }

            /* ---- GEMM1 + conv-store interleave (8 indep S accumulators) ---- */
            float S[8][4];
            #pragma unroll
            for (int nt = 0; nt < 8; ++nt) {
                float2 tq = *(const float2*)&qbp[nt * 8 + (lane & 3) * 2];
                S[nt][0] = tq.x; S[nt][1] = tq.y;
                S[nt][2] = tq.x; S[nt][3] = tq.y;
            }
            #pragma unroll
            for (int kt = 0; kt < 8; ++kt) {
                uint32_t bh[4][4];
                #pragma unroll
                for (int np = 0; np < 4; ++np) {
                    int key = np * 16 + b1_key;
                    int ch  = kt * 2 + b1_cs;
                    LDSM4(bh[np], bufR + key * 256 + ((ch ^ (key & 7)) << 4));
                }
                #pragma unroll
                for (int np = 0; np < 4; ++np) {
                    MMA(S[2 * np],     aQh[kt], &bh[np][0]);
                    MMA(S[2 * np + 1], aQh[kt], &bh[np][2]);
                }
                #pragma unroll
                for (int np = 0; np < 4; ++np) {
                    MMA(S[2 * np],     aQl[kt], &bh[np][0]);
                    MMA(S[2 * np + 1], aQl[kt], &bh[np][2]);
                }
                #pragma unroll
                for (int np = 0; np < 4; ++np) {   /* reuse regs for Kl */
                    int key = np * 16 + b1_key;
                    int ch  = kt * 2 + b1_cs;
                    LDSM4(bh[np], bufR + OFF_KL_REL + key * 256 + ((ch ^ (key & 7)) << 4));
                }
                #pragma unroll
                for (int np = 0; np < 4; ++np) {
                    MMA(S[2 * np],     aQh[kt], &bh[np][0]);
                    MMA(S[2 * np + 1], aQh[kt], &bh[np][2]);
                }
                /* hide conversion of tile t+2's chunk under the MMA burst */
                if (has_next && (kt & 1)) {
                    const int i = kt >> 1;
                    int row = srow + 16 * i;
                    uint32_t h0, l0, h1, l1, h2, l2, h3, l3;
                    split2(sA[i].x, sA[i].y, h0, l0); split2(sA[i].z, sA[i].w, h1, l1);
                    split2(sB[i].x, sB[i].y, h2, l2); split2(sB[i].z, sB[i].w, h3, l3);
                    uint32_t off = row * 256 + ((sch ^ (row & 7)) << 4);
                    *(uint4*)(smem + bufW + off)              = make_uint4(h0, h1, h2, h3);
                    *(uint4*)(smem + bufW + OFF_KL_REL + off) = make_uint4(l0, l1, l2, l3);
                }
            }
            if (has_next && tid < BN)
                ((float*)(smem + OFF_QB + ((t + 2) & 3) * 256))[tid] = sqb;

            /* ---- one-time static scale (full S needed) ---- */
            if (t == 0) {
                float mx0 = -INFINITY, mx1 = -INFINITY;
                #pragma unroll
                for (int nt = 0; nt < 8; ++nt) {
                    mx0 = fmaxf(mx0, fmaxf(S[nt][0], S[nt][1]));
                    mx1 = fmaxf(mx1, fmaxf(S[nt][2], S[nt][3]));
                }
                mx0 = fmaxf(mx0, __shfl_xor_sync(0xffffffffu, mx0, 1));
                mx0 = fmaxf(mx0, __shfl_xor_sync(0xffffffffu, mx0, 2));
                mx1 = fmaxf(mx1, __shfl_xor_sync(0xffffffffu, mx1, 1));
                mx1 = fmaxf(mx1, __shfl_xor_sync(0xffffffffu, mx1, 2));
                msc0 = mx0; msc1 = mx1;
            }

            /* ---- fused softmax-chunk + GEMM2 per 16-key group ---- */
            #pragma unroll
            for (int kt2 = 0; kt2 < 4; ++kt2) {
                uint32_t aP[4];
                {
                    float p0 = ex2(S[2 * kt2][0] - msc0);
                    float p1 = ex2(S[2 * kt2][1] - msc0);
                    float p2 = ex2(S[2 * kt2][2] - msc1);
                    float p3 = ex2(S[2 * kt2][3] - msc1);
                    float p4 = ex2(S[2 * kt2 + 1][0] - msc0);
                    float p5 = ex2(S[2 * kt2 + 1][1] - msc0);
                    float p6 = ex2(S[2 * kt2 + 1][2] - msc1);
                    float p7 = ex2(S[2 * kt2 + 1][3] - msc1);
                    l0r += (p0 + p1) + (p4 + p5);
                    l1r += (p2 + p3) + (p6 + p7);
                    pm0 = fmaxf(pm0, fmaxf(fmaxf(p0, p1), fmaxf(p4, p5)));
                    pm1 = fmaxf(pm1, fmaxf(fmaxf(p2, p3), fmaxf(p6, p7)));
                    aP[0] = pack_bf16x2(p0, p1);
                    aP[1] = pack_bf16x2(p2, p3);
                    aP[2] = pack_bf16x2(p4, p5);
                    aP[3] = pack_bf16x2(p6, p7);
                }
                const int key = kt2 * 16 + b2_key;
                const uint32_t krow = bufR + key * 256;
                #pragma unroll
                for (int dp = 0; dp < 8; ++dp) {
                    uint32_t bv[4];
                    int ch = dp * 2 + b2_cs;
                    LDSM4T(bv, krow + ((ch ^ (key & 7)) << 4));
                    MMA(O[2 * dp],     aP, &bv[0]);
                    MMA(O[2 * dp + 1], aP, &bv[2]);
                }
            }
        }

        /* ---- segment epilogue: reduce l/pm, write slot ---- */
        {
            l0r += __shfl_xor_sync(0xffffffffu, l0r, 1);
            l0r += __shfl_xor_sync(0xffffffffu, l0r, 2);
            l1r += __shfl_xor_sync(0xffffffffu, l1r, 1);
            l1r += __shfl_xor_sync(0xffffffffu, l1r, 2);
            pm0 = fmaxf(pm0, __shfl_xor_sync(0xffffffffu, pm0, 1));
            pm0 = fmaxf(pm0, __shfl_xor_sync(0xffffffffu, pm0, 2));
            pm1 = fmaxf(pm1, __shfl_xor_sync(0xffffffffu, pm1, 1));
            pm1 = fmaxf(pm1, __shfl_xor_sync(0xffffffffu, pm1, 2));

            int r1 = row0 + m0 + (lane >> 2);
            int r2 = r1 + 8;
            if ((lane & 3) == 0) {
                g_ml[(size_t)slot * T_DIM + r1] = make_float4(msc0, pm0, l0r, 0.f);
                g_ml[(size_t)slot * T_DIM + r2] = make_float4(msc1, pm1, l1r, 0.f);
            }
            float* o1 = g_O + ((size_t)slot * T_DIM + r1) * D_DIM + (lane & 3) * 2;
            float* o2 = g_O + ((size_t)slot * T_DIM + r2) * D_DIM + (lane & 3) * 2;
            #pragma unroll
            for (int nt = 0; nt < 16; ++nt) {
                *(float2*)(o1 + nt * 8) = make_float2(O[nt][0], O[nt][1]);
                *(float2*)(o2 + nt * 8) = make_float2(O[nt][2], O[nt][3]);
            }
        }
        ft = tend;
    }
}

/* ============ K2: combine slots, write out cols [0,384), emit b, h partials ============ */
__global__ void combine_kernel(const float* __restrict__ x, float* __restrict__ out) {
    __shared__ float stage[8 * 128];
    int row  = blockIdx.x * 8 + (threadIdx.x >> 5);
    int warp = threadIdx.x >> 5;
    int lane = threadIdx.x & 31;
    float4 ml[4];
    float M = -INFINITY;
    #pragma unroll
    for (int s = 0; s < 4; ++s) {
        ml[s] = g_ml[(size_t)s * T_DIM + row];
        if (ml[s].z != 0.f) M = fmaxf(M, ml[s].x);
    }
    float L = 0.f, bmax = 0.f;
    float4 U = make_float4(0.f, 0.f, 0.f, 0.f);
    #pragma unroll
    for (int s = 0; s < 4; ++s) {
        if (ml[s].z != 0.f) {          /* warp-uniform branch */
            float e = ex2(ml[s].x - M);
            L += ml[s].z * e;
            bmax = fmaxf(bmax, ml[s].y * e);
            float4 o = *(const float4*)&g_O[((size_t)s * T_DIM + row) * D_DIM + lane * 4];
            U.x += o.x * e; U.y += o.y * e; U.z += o.z * e; U.w += o.w * e;
        }
    }
    float invL = 1.0f / L;
    U.x *= invL; U.y *= invL; U.z *= invL; U.w *= invL;
    float4 c = *(const float4*)&x[(size_t)row * D_DIM + lane * 4];
    float* orow = out + (size_t)row * (4 * D_DIM);
    *(float4*)&orow[lane * 4]             = c;
    *(float4*)&orow[D_DIM + lane * 4]     = U;
    *(float4*)&orow[2 * D_DIM + lane * 4] = make_float4(c.x * U.x, c.y * U.y, c.z * U.z, c.w * U.w);
    float b = bmax * invL;                 /* lane-uniform */
    if (lane == 0) g_b[row] = b;
    /* h partial: this block's 8 rows */
    *(float4*)&stage[warp * 128 + lane * 4] = make_float4(b * c.x, b * c.y, b * c.z, b * c.w);
    __syncthreads();
    if (threadIdx.x < 128) {
        float s = 0.f;
        #pragma unroll
        for (int ww = 0; ww < 8; ++ww) s += stage[ww * 128 + threadIdx.x];
        g_hpart[blockIdx.x * 128 + threadIdx.x] = s;
    }
}

/* ============ K3a/K3b: two-stage deterministic h reduction ============ */
__global__ void hreduce1_kernel() {
    int d = threadIdx.x;
    int b0 = blockIdx.x * 16;
    float s = 0.f;
    #pragma unroll
    for (int i = 0; i < 16; ++i) s += g_hpart[(size_t)(b0 + i) * 128 + d];
    g_h2[blockIdx.x * 128 + d] = s;
}
__global__ void hreduce2_kernel() {
    int d = threadIdx.x;
    float s = 0.f;
    #pragma unroll
    for (int b = 0; b < 64; ++b) s += g_h2[b * 128 + d];
    g_h[d] = s;
}
__global__ void hwrite_kernel(const float* __restrict__ x, float* __restrict__ out) {
    int idx = blockIdx.x * blockDim.x + threadIdx.x;
    int row = idx >> 5;
    int dq  = idx & 31;
    float4 c = ((const float4*)x)[(size_t)row * 32 + dq];
    float4 h = ((const float4*)g_h)[dq];
    ((float4*)out)[(size_t)row * 128 + 96 + dq] =
        make_float4(c.x * h.x, c.y * h.y, c.z * h.z, c.w * h.w);
}

/* ============================================================================ */
extern "C" void kernel_launch(void* const* d_in, const int* in_sizes, int n_in,
                              void* d_out, int out_size) {
    const float* x    = (const float*)d_in[0];
    const float* kern = (const float*)d_in[1];
    float* out = (float*)d_out;

    cudaFuncSetAttribute(flash_kernel, cudaFuncAttributeMaxDynamicSharedMemorySize, SMEM_SZ);

    qbias_kernel<<<T_DIM / 8, 256>>>(x, kern);
    flash_kernel<<<NCTA, NTH, SMEM_SZ>>>(x, kern);
    combine_kernel<<<T_DIM / 8, 256>>>(x, out);
    hreduce1_kernel<<<64, 128>>>();
    hreduce2_kernel<<<1, 128>>>();
    hwrite_kernel<<<(T_DIM * D_DIM / 4) / 256, 256>>>(x, out);
}